// round 14
// baseline (speedup 1.0000x reference)
#include <cuda_runtime.h>
#include <math.h>

#define MAXDIM 1024
#define NT 512
#define NW 16
#define POOLSZ 65536

// Scratch (device globals; no allocation allowed)
__device__ float g_Dm[MAXDIM * MAXDIM];   // symmetric merged-distance matrix
__device__ int   g_pool[POOLSZ];          // leaf-list pool (capacity-doubling extents)
__device__ float g_vals[MAXDIM];
__device__ int   g_idx[MAXDIM];
__device__ int   g_node[MAXDIM];          // slot -> node id (merge iter) or -1 (leaf)
__device__ int   g_parent[MAXDIM];        // node -> parent node id (-1 root)
__device__ int   g_take[MAXDIM];          // node -> take flag
__device__ int   g_cov[MAXDIM];           // node -> covered flag (computed at end)
__device__ int4  g_rec[MAXDIM];           // node -> {aOff, aLen, bOff, bLen}
__device__ unsigned g_msim;               // flip-encoded max(X)
__device__ unsigned g_mabs;               // flip-encoded max|X|

__device__ __forceinline__ unsigned fflip(float f) {
    unsigned u = __float_as_uint(f);
    return (u & 0x80000000u) ? ~u : (u | 0x80000000u);
}
__device__ __forceinline__ float funflip(unsigned u) {
    return __uint_as_float((u & 0x80000000u) ? (u & 0x7FFFFFFFu) : ~u);
}

__global__ void k_reset() { g_msim = 0u; g_mabs = 0u; }

__global__ void k_maxred(const float* __restrict__ X, int n) {
    float mx = -3.402823466e38f, ma = 0.f;
    for (int i = blockIdx.x * blockDim.x + threadIdx.x; i < n; i += gridDim.x * blockDim.x) {
        float x = X[i];
        mx = fmaxf(mx, x);
        ma = fmaxf(ma, fabsf(x));
    }
    #pragma unroll
    for (int o = 16; o; o >>= 1) {
        mx = fmaxf(mx, __shfl_down_sync(~0u, mx, o));
        ma = fmaxf(ma, __shfl_down_sync(~0u, ma, o));
    }
    __shared__ float smx[8], sma[8];
    int w = threadIdx.x >> 5, l = threadIdx.x & 31;
    if (l == 0) { smx[w] = mx; sma[w] = ma; }
    __syncthreads();
    if (threadIdx.x == 0) {
        int nw = blockDim.x >> 5;
        for (int i = 1; i < nw; i++) { mx = fmaxf(mx, smx[i]); ma = fmaxf(ma, sma[i]); }
        atomicMax(&g_msim, fflip(mx));
        atomicMax(&g_mabs, fflip(ma));
    }
}

// One block per row r: build Dsym row, R row (identity), initial (rowmin, argmin), pool
__global__ void k_init(const float* __restrict__ X, float* __restrict__ R, int D) {
    int r = blockIdx.x;
    float msim = funflip(g_msim);
    float MAXD = __fmul_rn(funflip(g_mabs), 1000.0f);
    float bv = MAXD; int bbi = 0;
    for (int k = threadIdx.x; k < D; k += blockDim.x) {
        float x = X[(size_t)r * D + k];
        float d = (k == r) ? MAXD : __fsub_rn(msim, x);
        g_Dm[(size_t)r * D + k] = d;
        R[(size_t)r * D + k] = (k == r) ? 1.0f : 0.0f;
        float c = (k > r) ? d : MAXD;
        if (c < bv) { bv = c; bbi = k; }  // ascending k -> leftmost kept
    }
    #pragma unroll
    for (int o = 16; o; o >>= 1) {
        float ov = __shfl_down_sync(~0u, bv, o);
        int oi = __shfl_down_sync(~0u, bbi, o);
        if (ov < bv || (ov == bv && oi < bbi)) { bv = ov; bbi = oi; }
    }
    __shared__ float spv[8]; __shared__ int spi[8];
    int w = threadIdx.x >> 5, l = threadIdx.x & 31;
    if (l == 0) { spv[w] = bv; spi[w] = bbi; }
    __syncthreads();
    if (threadIdx.x == 0) {
        int nw = blockDim.x >> 5;
        for (int i = 1; i < nw; i++)
            if (spv[i] < bv || (spv[i] == bv && spi[i] < bbi)) { bv = spv[i]; bbi = spi[i]; }
        g_vals[r] = bv;
        g_idx[r] = bbi;
        g_pool[r] = r;   // singleton leaf list
        g_node[r] = -1;  // leaf slot
    }
}

// Persistent single-block HAC: 3 barriers/iter, pool leaf lists, fused m1-row min,
// pair-sum overlapped with row loads, NO R-writes in the loop (deferred paint).
__global__ void __launch_bounds__(NT, 1) k_hac(const float* __restrict__ W, int D) {
    __shared__ float s_vals[MAXDIM];
    __shared__ int   s_idx[MAXDIM];
    __shared__ float s_cs[MAXDIM];
    __shared__ float s_within[MAXDIM];
    __shared__ float s_energy[MAXDIM];
    __shared__ int   s_off[MAXDIM], s_len[MAXDIM], s_cap[MAXDIM];
    __shared__ int   s_rlist[MAXDIM];
    __shared__ float s_cv[MAXDIM];
    __shared__ int   s_ci[MAXDIM];
    __shared__ unsigned s_amask[MAXDIM / 32];
    __shared__ float s_pv[NW]; __shared__ int s_pi[NW];
    __shared__ float s_mv[NW]; __shared__ int s_mi[NW];
    __shared__ float s_pw[NW];
    __shared__ int s_m1, s_m2, s_nresc, s_ptop;
    __shared__ float s_cs1, s_cs2, s_ncs;

    const int j = threadIdx.x;
    const int wid = j >> 5, lane = j & 31;
    const float MAXD = __fmul_rn(funflip(g_mabs), 1000.0f);
    const int e0 = 2 * j, e1 = 2 * j + 1;
    const bool evenD = ((D & 1) == 0);
    const bool vec4 = ((D & 3) == 0);
    const int NEUT = 0x3FFFFFFF;

    for (int k = j; k < MAXDIM; k += NT) {
        if (k < D) {
            s_vals[k] = g_vals[k]; s_idx[k] = g_idx[k];
            s_cs[k] = 1.0f; s_within[k] = 0.f; s_energy[k] = 0.f;
            s_off[k] = k; s_len[k] = 1; s_cap[k] = 1;
        } else { s_vals[k] = MAXD; s_idx[k] = 0; }
    }
    if (j < MAXDIM / 32) {
        int lo = j * 32; unsigned m = 0u;
        if (D >= lo + 32) m = 0xFFFFFFFFu;
        else if (D > lo) m = (1u << (D - lo)) - 1u;
        s_amask[j] = m;
    }
    if (j == 0) { s_ptop = D; s_nresc = 0; }
    __syncthreads();

    // ---- prologue: select merge 0
    {
        float v = MAXD; int bi = NEUT;
        if (e0 < D) { float x = s_vals[e0]; if (x < v) { v = x; bi = e0; } }
        if (e1 < D) { float x = s_vals[e1]; if (x < v) { v = x; bi = e1; } }
        #pragma unroll
        for (int o = 16; o; o >>= 1) {
            float ov = __shfl_down_sync(~0u, v, o);
            int oi = __shfl_down_sync(~0u, bi, o);
            if (ov < v || (ov == v && oi < bi)) { v = ov; bi = oi; }
        }
        if (lane == 0) { s_pv[wid] = v; s_pi[wid] = bi; }
    }
    __syncthreads();
    if (wid == 0) {
        float v = (lane < NW) ? s_pv[lane] : MAXD;
        int bi = (lane < NW) ? s_pi[lane] : NEUT;
        #pragma unroll
        for (int o = 16; o; o >>= 1) {
            float ov = __shfl_down_sync(~0u, v, o);
            int oi = __shfl_down_sync(~0u, bi, o);
            if (ov < v || (ov == v && oi < bi)) { v = ov; bi = oi; }
        }
        if (lane == 0) {
            if (bi >= D) bi = 0;
            int m1 = bi, m2 = s_idx[bi];
            s_m1 = m1; s_m2 = m2;
            float c1 = s_cs[m1], c2 = s_cs[m2];
            float ncs = __fadd_rn(c1, c2);
            s_cs1 = c1; s_cs2 = c2; s_ncs = ncs;
            s_cs[m1] = ncs;
            s_vals[m2] = MAXD;
            s_amask[m2 >> 5] &= ~(1u << (m2 & 31));
        }
    }
    __syncthreads();

    for (int it = 0; it < D - 1; ++it) {
        const int m1 = s_m1, m2 = s_m2;
        const float cs1 = s_cs1, cs2 = s_cs2, ncs = s_ncs;
        const bool inr = (e0 < D);

        // ==== Region1: row loads + overlapped pair-sum + maintenance + m1-row min
        float d10 = MAXD, d11 = MAXD, d20 = MAXD, d21 = MAXD;
        unsigned am = 0u;
        if (inr) {
            am = (s_amask[e0 >> 5] >> (e0 & 31)) & 0x3u;
            if (evenD && e1 < D) {
                float2 t1 = *(const float2*)&g_Dm[(size_t)m1 * D + e0];
                float2 t2 = *(const float2*)&g_Dm[(size_t)m2 * D + e0];
                d10 = t1.x; d11 = t1.y; d20 = t2.x; d21 = t2.y;
            } else {
                d10 = g_Dm[(size_t)m1 * D + e0];
                d20 = g_Dm[(size_t)m2 * D + e0];
                if (e1 < D) { d11 = g_Dm[(size_t)m1 * D + e1]; d21 = g_Dm[(size_t)m2 * D + e1]; }
            }
        }

        // cross-energy pair sum (overlaps the row-load latency above)
        {
            float ps = 0.f;
            int aOff = s_off[m1], aLen = s_len[m1];
            int bOff = s_off[m2], bLen = s_len[m2];
            for (int ia = wid; ia < aLen; ia += NW) {
                int a = g_pool[aOff + ia];
                for (int ib = lane; ib < bLen; ib += 32) {
                    int b = g_pool[bOff + ib];
                    int lo = a < b ? a : b, hi = a < b ? b : a;
                    ps = __fadd_rn(ps, __ldg(&W[(size_t)lo * D + hi]));
                }
            }
            #pragma unroll
            for (int o = 16; o; o >>= 1) ps = __fadd_rn(ps, __shfl_down_sync(~0u, ps, o));
            if (lane == 0) s_pw[wid] = ps;
        }

        unsigned needmask = 0u;
        float nv0 = MAXD, nv1 = MAXD;
        float m1best = MAXD; int m1bi = NEUT;
        if (am & 1u) {
            if (e0 != m1) {
                nv0 = __fdiv_rn(__fadd_rn(__fmul_rn(d10, cs1), __fmul_rn(d20, cs2)), ncs);
                float vold = s_vals[e0]; int iold = s_idx[e0];
                if (iold == m2) needmask |= 1u;
                else if (m1 > e0) {
                    if (iold == m1) {
                        if (nv0 <= vold) s_vals[e0] = nv0; else needmask |= 1u;
                    } else {
                        if (nv0 < vold) { s_vals[e0] = nv0; s_idx[e0] = m1; }
                        else if (nv0 == vold && m1 < iold) s_idx[e0] = m1;
                    }
                }
                if (e0 > m1 && nv0 < m1best) { m1best = nv0; m1bi = e0; }
            }
        }
        if (am & 2u) {
            if (e1 != m1) {
                nv1 = __fdiv_rn(__fadd_rn(__fmul_rn(d11, cs1), __fmul_rn(d21, cs2)), ncs);
                float vold = s_vals[e1]; int iold = s_idx[e1];
                if (iold == m2) needmask |= 2u;
                else if (m1 > e1) {
                    if (iold == m1) {
                        if (nv1 <= vold) s_vals[e1] = nv1; else needmask |= 2u;
                    } else {
                        if (nv1 < vold) { s_vals[e1] = nv1; s_idx[e1] = m1; }
                        else if (nv1 == vold && m1 < iold) s_idx[e1] = m1;
                    }
                }
                if (e1 > m1 && nv1 < m1best) { m1best = nv1; m1bi = e1; }
            }
        }
        if (inr) {
            if (evenD && e1 < D) {
                float2 t; t.x = nv0; t.y = nv1;
                *(float2*)&g_Dm[(size_t)m1 * D + e0] = t;
            } else {
                g_Dm[(size_t)m1 * D + e0] = nv0;
                if (e1 < D) g_Dm[(size_t)m1 * D + e1] = nv1;
            }
            if ((am & 1u) && e0 != m1) g_Dm[(size_t)e0 * D + m1] = nv0;
            if ((am & 2u) && e1 != m1) g_Dm[(size_t)e1 * D + m1] = nv1;
        }
        // fused m1-row min partials
        #pragma unroll
        for (int o = 16; o; o >>= 1) {
            float ov = __shfl_down_sync(~0u, m1best, o);
            int oi = __shfl_down_sync(~0u, m1bi, o);
            if (ov < m1best || (ov == m1best && oi < m1bi)) { m1best = ov; m1bi = oi; }
        }
        if (lane == 0) { s_mv[wid] = m1best; s_mi[wid] = m1bi; }
        if (needmask & 1u) { int p = atomicAdd(&s_nresc, 1); s_rlist[p] = e0; }
        if (needmask & 2u) { int p = atomicAdd(&s_nresc, 1); s_rlist[p] = e1; }
        __syncthreads();   // B1

        // ==== Region2: owner-masked argmin pre-reduce + rescans
        {
            float v = MAXD; int bi = NEUT;
            if (e0 < D && !(needmask & 1u) && e0 != m1) {
                float x = s_vals[e0];
                if (x < v) { v = x; bi = e0; }
            }
            if (e1 < D && !(needmask & 2u) && e1 != m1) {
                float x = s_vals[e1];
                if (x < v) { v = x; bi = e1; }
            }
            #pragma unroll
            for (int o = 16; o; o >>= 1) {
                float ov = __shfl_down_sync(~0u, v, o);
                int oi = __shfl_down_sync(~0u, bi, o);
                if (ov < v || (ov == v && oi < bi)) { v = ov; bi = oi; }
            }
            if (lane == 0) { s_pv[wid] = v; s_pi[wid] = bi; }
        }
        {
            int nr = s_nresc;
            for (int t = wid; t < nr; t += NW) {
                int r = s_rlist[t];
                float bv = MAXD; int bbi = 0;
                if (vec4) {
                    const float4* row4 = reinterpret_cast<const float4*>(&g_Dm[(size_t)r * D]);
                    float4 qd[8];
                    #pragma unroll
                    for (int c = 0; c < 8; c++) {
                        int k = c * 128 + lane * 4;
                        if (k < D) qd[c] = row4[k >> 2];
                        else { qd[c].x = MAXD; qd[c].y = MAXD; qd[c].z = MAXD; qd[c].w = MAXD; }
                    }
                    #pragma unroll
                    for (int c = 0; c < 8; c++) {
                        int k = c * 128 + lane * 4;
                        unsigned a2 = (k < D) ? (s_amask[k >> 5] >> (k & 31)) : 0u;
                        float f0 = ((a2 & 1u) && k > r)       ? qd[c].x : MAXD;
                        float f1 = ((a2 & 2u) && (k + 1) > r) ? qd[c].y : MAXD;
                        float f2 = ((a2 & 4u) && (k + 2) > r) ? qd[c].z : MAXD;
                        float f3 = ((a2 & 8u) && (k + 3) > r) ? qd[c].w : MAXD;
                        if (f0 < bv) { bv = f0; bbi = k; }
                        if (f1 < bv) { bv = f1; bbi = k + 1; }
                        if (f2 < bv) { bv = f2; bbi = k + 2; }
                        if (f3 < bv) { bv = f3; bbi = k + 3; }
                    }
                } else {
                    const float* row = &g_Dm[(size_t)r * D];
                    for (int k = lane; k < D; k += 32) {
                        int alv = (s_amask[k >> 5] >> (k & 31)) & 1;
                        float vv = (alv && k > r) ? row[k] : MAXD;
                        if (vv < bv) { bv = vv; bbi = k; }
                    }
                }
                #pragma unroll
                for (int o = 16; o; o >>= 1) {
                    float ov = __shfl_down_sync(~0u, bv, o);
                    int oi = __shfl_down_sync(~0u, bbi, o);
                    if (ov < bv || (ov == bv && oi < bbi)) { bv = ov; bbi = oi; }
                }
                if (lane == 0) {
                    s_vals[r] = bv; s_idx[r] = bbi;
                    s_cv[t] = bv; s_ci[t] = r;
                }
            }
        }
        __syncthreads();   // B2

        // ==== Region3 (warp 0): reduces + take + records + pool merge + next selection
        if (wid == 0) {
            float cw = (lane < NW) ? s_pw[lane] : 0.f;
            #pragma unroll
            for (int o = 16; o; o >>= 1) cw = __fadd_rn(cw, __shfl_down_sync(~0u, cw, o));

            float mv = (lane < NW) ? s_mv[lane] : MAXD;
            int mi = (lane < NW) ? s_mi[lane] : NEUT;
            #pragma unroll
            for (int o = 16; o; o >>= 1) {
                float ov = __shfl_down_sync(~0u, mv, o);
                int oi = __shfl_down_sync(~0u, mi, o);
                if (ov < mv || (ov == mv && oi < mi)) { mv = ov; mi = oi; }
            }

            float gv = (lane < NW) ? s_pv[lane] : MAXD;
            int gi = (lane < NW) ? s_pi[lane] : NEUT;
            int nr2 = s_nresc;
            for (int t = lane; t < nr2; t += 32) {
                float cv = s_cv[t]; int ci = s_ci[t];
                if (cv < gv || (cv == gv && ci < gi)) { gv = cv; gi = ci; }
            }
            #pragma unroll
            for (int o = 16; o; o >>= 1) {
                float ov = __shfl_down_sync(~0u, gv, o);
                int oi = __shfl_down_sync(~0u, gi, o);
                if (ov < gv || (ov == gv && oi < gi)) { gv = ov; gi = oi; }
            }

            int dst = 0, src = 0, ncopy = 0, dst2 = 0, src2 = 0, ncopy2 = 0;
            if (lane == 0) {
                if (mi >= D) mi = 0;
                s_vals[m1] = mv; s_idx[m1] = mi;
                if (mv < gv || (mv == gv && m1 < gi)) { gv = mv; gi = m1; }
                if (gi >= D) gi = 0;
                // take decision
                float me = __fadd_rn(__fadd_rn(s_within[m1], s_within[m2]), cw);
                float es = __fadd_rn(s_energy[m1], s_energy[m2]);
                int take = (me >= es) ? 1 : 0;
                s_within[m1] = me;
                s_energy[m1] = take ? me : es;
                // record merge node (extents BEFORE mutation)
                int aLen = s_len[m1], bLen = s_len[m2], lenN = aLen + bLen;
                int aOff = s_off[m1], bOff = s_off[m2];
                g_rec[it] = make_int4(aOff, aLen, bOff, bLen);
                g_take[it] = take;
                g_parent[it] = -1;
                int na = g_node[m1], nb = g_node[m2];
                if (na >= 0) g_parent[na] = it;
                if (nb >= 0) g_parent[nb] = it;
                g_node[m1] = it;
                // leaf-list merge plan
                if (lenN <= s_cap[m1]) {
                    dst = aOff + aLen; src = bOff; ncopy = bLen;
                } else if (lenN <= s_cap[m2]) {
                    dst = bOff + bLen; src = aOff; ncopy = aLen;
                    s_off[m1] = bOff; s_cap[m1] = s_cap[m2];
                } else {
                    int nc = 1; while (nc < lenN) nc <<= 1;
                    int nb2 = s_ptop; s_ptop = nb2 + nc;
                    dst = nb2; src = aOff; ncopy = aLen;
                    dst2 = nb2 + aLen; src2 = bOff; ncopy2 = bLen;
                    s_off[m1] = nb2; s_cap[m1] = nc;
                }
                s_len[m1] = lenN;
                // next merge selection (last iteration: harmless)
                int n1 = gi, n2 = s_idx[n1];
                s_m1 = n1; s_m2 = n2;
                float c1 = s_cs[n1], c2 = s_cs[n2];
                float nn = __fadd_rn(c1, c2);
                s_cs1 = c1; s_cs2 = c2; s_ncs = nn;
                s_cs[n1] = nn;
                s_vals[n2] = MAXD;
                s_amask[n2 >> 5] &= ~(1u << (n2 & 31));
                s_nresc = 0;
            }
            dst = __shfl_sync(~0u, dst, 0);   src = __shfl_sync(~0u, src, 0);
            ncopy = __shfl_sync(~0u, ncopy, 0);
            dst2 = __shfl_sync(~0u, dst2, 0); src2 = __shfl_sync(~0u, src2, 0);
            ncopy2 = __shfl_sync(~0u, ncopy2, 0);
            for (int t = lane; t < ncopy; t += 32) g_pool[dst + t] = g_pool[src + t];
            for (int t = lane; t < ncopy2; t += 32) g_pool[dst2 + t] = g_pool[src2 + t];
        }
        __syncthreads();   // B3
    }

    // ==== coverage pass: cov[it] = take[it] || cov[parent[it]]  (parent > it)
    // preload take/parent into SMEM (reuse s_rlist / s_ci), serial pass by thread 0
    for (int k = j; k < D - 1; k += NT) { s_rlist[k] = g_parent[k]; s_ci[k] = g_take[k]; }
    __syncthreads();
    if (j == 0) {
        for (int n = D - 2; n >= 0; --n) {
            int p = s_rlist[n];
            int c = s_ci[n];
            if (!c && p >= 0) c = s_idx[p];   // s_idx reused as cov array
            s_idx[n] = c;
        }
    }
    __syncthreads();
    for (int k = j; k < D - 1; k += NT) g_cov[k] = s_idx[k];
}

// Paint: one block per merge node; covered nodes write their A x B cross block.
__global__ void k_paint(float* __restrict__ R, int D) {
    int n = blockIdx.x;
    if (!g_cov[n]) return;
    int4 rc = g_rec[n];
    int wid = threadIdx.x >> 5, lane = threadIdx.x & 31;
    for (int ia = wid; ia < rc.y; ia += 8) {
        int a = g_pool[rc.x + ia];
        float* ra = R + (size_t)a * D;
        for (int ib = lane; ib < rc.w; ib += 32) {
            int b = g_pool[rc.z + ib];
            ra[b] = 1.0f;
            R[(size_t)b * D + a] = 1.0f;
        }
    }
}

extern "C" void kernel_launch(void* const* d_in, const int* in_sizes, int n_in,
                              void* d_out, int out_size) {
    const float* X = (const float*)d_in[0];
    const float* W = (const float*)d_in[1];
    float* R = (float*)d_out;
    int n = in_sizes[0];
    int D = (int)(sqrt((double)n) + 0.5);
    if (D < 2 || D > MAXDIM) return;

    k_reset<<<1, 1>>>();
    k_maxred<<<256, 256>>>(X, n);
    k_init<<<D, 256>>>(X, R, D);
    k_hac<<<1, NT>>>(W, D);
    k_paint<<<D - 1, 256>>>(R, D);
}

// round 17
// speedup vs baseline: 1.3309x; 1.3309x over previous
#include <cuda_runtime.h>
#include <math.h>

#define MAXDIM 1024
#define NT 512
#define NW 16
#define POOLSZ 65536
#define NEUT 0x3FFFFFFF

// Scratch (device globals; no allocation allowed)
__device__ float g_Dm[MAXDIM * MAXDIM];   // symmetric merged-distance matrix
__device__ int   g_pool[POOLSZ];          // leaf-list pool (capacity-doubling extents)
__device__ float g_vals[MAXDIM];
__device__ int   g_idx[MAXDIM];
__device__ int   g_node[MAXDIM];          // slot -> node id (merge iter) or -1 (leaf)
__device__ int   g_parent[MAXDIM];        // node -> parent node id (-1 root)
__device__ int   g_take[MAXDIM];          // node -> take flag
__device__ int   g_cov[MAXDIM];           // node -> covered flag
__device__ int4  g_rec[MAXDIM];           // node -> {aOff, aLen, bOff, bLen}
__device__ unsigned g_msim;
__device__ unsigned g_mabs;

__device__ __forceinline__ unsigned fflip(float f) {
    unsigned u = __float_as_uint(f);
    return (u & 0x80000000u) ? ~u : (u | 0x80000000u);
}
__device__ __forceinline__ float funflip(unsigned u) {
    return __uint_as_float((u & 0x80000000u) ? (u & 0x7FFFFFFFu) : ~u);
}
// Warp argmin via redux: min value, leftmost (min) index on ties. All lanes get result.
__device__ __forceinline__ void wargmin(float v, int i, float& ov, int& oi) {
    unsigned b = fflip(v);
    unsigned mb = __reduce_min_sync(0xFFFFFFFFu, b);
    unsigned cand = (b == mb) ? (unsigned)i : (unsigned)NEUT;
    oi = (int)__reduce_min_sync(0xFFFFFFFFu, cand);
    ov = funflip(mb);
}

__global__ void k_reset() { g_msim = 0u; g_mabs = 0u; }

__global__ void k_maxred(const float* __restrict__ X, int n) {
    float mx = -3.402823466e38f, ma = 0.f;
    for (int i = blockIdx.x * blockDim.x + threadIdx.x; i < n; i += gridDim.x * blockDim.x) {
        float x = X[i];
        mx = fmaxf(mx, x);
        ma = fmaxf(ma, fabsf(x));
    }
    #pragma unroll
    for (int o = 16; o; o >>= 1) {
        mx = fmaxf(mx, __shfl_down_sync(~0u, mx, o));
        ma = fmaxf(ma, __shfl_down_sync(~0u, ma, o));
    }
    __shared__ float smx[8], sma[8];
    int w = threadIdx.x >> 5, l = threadIdx.x & 31;
    if (l == 0) { smx[w] = mx; sma[w] = ma; }
    __syncthreads();
    if (threadIdx.x == 0) {
        int nw = blockDim.x >> 5;
        for (int i = 1; i < nw; i++) { mx = fmaxf(mx, smx[i]); ma = fmaxf(ma, sma[i]); }
        atomicMax(&g_msim, fflip(mx));
        atomicMax(&g_mabs, fflip(ma));
    }
}

__global__ void k_init(const float* __restrict__ X, float* __restrict__ R, int D) {
    int r = blockIdx.x;
    float msim = funflip(g_msim);
    float MAXD = __fmul_rn(funflip(g_mabs), 1000.0f);
    float bv = MAXD; int bbi = 0;
    for (int k = threadIdx.x; k < D; k += blockDim.x) {
        float x = X[(size_t)r * D + k];
        float d = (k == r) ? MAXD : __fsub_rn(msim, x);
        g_Dm[(size_t)r * D + k] = d;
        R[(size_t)r * D + k] = (k == r) ? 1.0f : 0.0f;
        float c = (k > r) ? d : MAXD;
        if (c < bv) { bv = c; bbi = k; }
    }
    #pragma unroll
    for (int o = 16; o; o >>= 1) {
        float ov = __shfl_down_sync(~0u, bv, o);
        int oi = __shfl_down_sync(~0u, bbi, o);
        if (ov < bv || (ov == bv && oi < bbi)) { bv = ov; bbi = oi; }
    }
    __shared__ float spv[8]; __shared__ int spi[8];
    int w = threadIdx.x >> 5, l = threadIdx.x & 31;
    if (l == 0) { spv[w] = bv; spi[w] = bbi; }
    __syncthreads();
    if (threadIdx.x == 0) {
        int nw = blockDim.x >> 5;
        for (int i = 1; i < nw; i++)
            if (spv[i] < bv || (spv[i] == bv && spi[i] < bbi)) { bv = spv[i]; bbi = spi[i]; }
        g_vals[r] = bv;
        g_idx[r] = bbi;
        g_pool[r] = r;
        g_node[r] = -1;
    }
}

// Persistent single-block HAC: redux argmins, 2-3 barriers/iter,
// region3 parallelized across warps 0/1/2, deferred R paint.
__global__ void __launch_bounds__(NT, 1) k_hac(const float* __restrict__ W, int D) {
    __shared__ float s_vals[MAXDIM];
    __shared__ int   s_idx[MAXDIM];
    __shared__ float s_cs[MAXDIM];
    __shared__ float s_within[MAXDIM];
    __shared__ float s_energy[MAXDIM];
    __shared__ int   s_off[MAXDIM], s_len[MAXDIM], s_cap[MAXDIM];
    __shared__ int   s_rlist[MAXDIM];
    __shared__ float s_cv[MAXDIM];
    __shared__ int   s_ci[MAXDIM];
    __shared__ unsigned s_amask[MAXDIM / 32];
    __shared__ float s_pv[NW]; __shared__ int s_pi[NW];
    __shared__ float s_mv[NW]; __shared__ int s_mi[NW];
    __shared__ float s_pw[NW];
    __shared__ int s_m1, s_m2, s_nresc, s_ptop;
    __shared__ float s_cs1, s_cs2, s_ncs;

    const int j = threadIdx.x;
    const int wid = j >> 5, lane = j & 31;
    const float MAXD = __fmul_rn(funflip(g_mabs), 1000.0f);
    const int e0 = j, e1 = j + NT;
    const bool vec4 = ((D & 3) == 0);

    for (int k = j; k < MAXDIM; k += NT) {
        if (k < D) {
            s_vals[k] = g_vals[k]; s_idx[k] = g_idx[k];
            s_cs[k] = 1.0f; s_within[k] = 0.f; s_energy[k] = 0.f;
            s_off[k] = k; s_len[k] = 1; s_cap[k] = 1;
        } else { s_vals[k] = MAXD; s_idx[k] = 0; }
    }
    if (j < MAXDIM / 32) {
        int lo = j * 32; unsigned m = 0u;
        if (D >= lo + 32) m = 0xFFFFFFFFu;
        else if (D > lo) m = (1u << (D - lo)) - 1u;
        s_amask[j] = m;
    }
    if (j == 0) { s_ptop = D; s_nresc = 0; }
    int a0 = (e0 < D), a1 = (e1 < D);
    __syncthreads();

    // ---- prologue: select merge 0
    {
        float v = MAXD; int bi = NEUT;
        if (a0) { float x = s_vals[e0]; if (x < v) { v = x; bi = e0; } }
        if (a1) { float x = s_vals[e1]; if (x < v) { v = x; bi = e1; } }
        float rv; int ri;
        wargmin(v, bi, rv, ri);
        if (lane == 0) { s_pv[wid] = rv; s_pi[wid] = ri; }
    }
    __syncthreads();
    if (wid == 0) {
        float v = (lane < NW) ? s_pv[lane] : MAXD;
        int bi = (lane < NW) ? s_pi[lane] : NEUT;
        float rv; int ri;
        wargmin(v, bi, rv, ri);
        if (lane == 0) {
            if (ri >= D) ri = 0;
            int m1 = ri, m2 = s_idx[ri];
            s_m1 = m1; s_m2 = m2;
            float c1 = s_cs[m1], c2 = s_cs[m2];
            float ncs = __fadd_rn(c1, c2);
            s_cs1 = c1; s_cs2 = c2; s_ncs = ncs;
            s_cs[m1] = ncs;
            s_vals[m2] = MAXD;
            s_amask[m2 >> 5] &= ~(1u << (m2 & 31));
        }
    }
    __syncthreads();

    for (int it = 0; it < D - 1; ++it) {
        const int m1 = s_m1, m2 = s_m2;
        const float cs1 = s_cs1, cs2 = s_cs2, ncs = s_ncs;
        // register-captured extents (used by region1 pair-sum AND region3 warps 1/2)
        const int aOff = s_off[m1], aLen = s_len[m1];
        const int bOff = s_off[m2], bLen = s_len[m2];
        a0 &= (e0 != m2); a1 &= (e1 != m2);

        // ==== Region1: row loads + overlapped pair-sum + maintenance + local pre-reduce
        float d10 = MAXD, d11 = MAXD, d20 = MAXD, d21 = MAXD;
        if (e0 < D) { d10 = g_Dm[(size_t)m1 * D + e0]; d20 = g_Dm[(size_t)m2 * D + e0]; }
        if (e1 < D) { d11 = g_Dm[(size_t)m1 * D + e1]; d21 = g_Dm[(size_t)m2 * D + e1]; }

        // cross-energy pair sum (overlaps the row-load latency above)
        {
            float ps = 0.f;
            for (int ia = wid; ia < aLen; ia += NW) {
                int a = g_pool[aOff + ia];
                for (int ib = lane; ib < bLen; ib += 32) {
                    int b = g_pool[bOff + ib];
                    int lo = a < b ? a : b, hi = a < b ? b : a;
                    ps = __fadd_rn(ps, __ldg(&W[(size_t)lo * D + hi]));
                }
            }
            #pragma unroll
            for (int o = 16; o; o >>= 1) ps = __fadd_rn(ps, __shfl_down_sync(~0u, ps, o));
            if (lane == 0) s_pw[wid] = ps;
        }

        int need0 = 0, need1 = 0;
        float nv0 = MAXD, nv1 = MAXD;
        float v0f = MAXD, v1f = MAXD;        // final owned values (MAXD if rescanned/dead/m1)
        float m1best = MAXD; int m1bi = NEUT;
        if (a0 && e0 != m1) {
            nv0 = __fdiv_rn(__fadd_rn(__fmul_rn(d10, cs1), __fmul_rn(d20, cs2)), ncs);
            float vold = s_vals[e0]; int iold = s_idx[e0];
            if (iold == m2) need0 = 1;
            else if (m1 > e0) {
                if (iold == m1) {
                    if (nv0 <= vold) { s_vals[e0] = nv0; v0f = nv0; } else need0 = 1;
                } else {
                    if (nv0 < vold) { s_vals[e0] = nv0; s_idx[e0] = m1; v0f = nv0; }
                    else { v0f = vold; if (nv0 == vold && m1 < iold) s_idx[e0] = m1; }
                }
            } else v0f = vold;
            if (e0 > m1 && nv0 < m1best) { m1best = nv0; m1bi = e0; }
        }
        if (a1 && e1 != m1) {
            nv1 = __fdiv_rn(__fadd_rn(__fmul_rn(d11, cs1), __fmul_rn(d21, cs2)), ncs);
            float vold = s_vals[e1]; int iold = s_idx[e1];
            if (iold == m2) need1 = 1;
            else if (m1 > e1) {
                if (iold == m1) {
                    if (nv1 <= vold) { s_vals[e1] = nv1; v1f = nv1; } else need1 = 1;
                } else {
                    if (nv1 < vold) { s_vals[e1] = nv1; s_idx[e1] = m1; v1f = nv1; }
                    else { v1f = vold; if (nv1 == vold && m1 < iold) s_idx[e1] = m1; }
                }
            } else v1f = vold;
            if (e1 > m1 && nv1 < m1best) { m1best = nv1; m1bi = e1; }
        }
        if (e0 < D) g_Dm[(size_t)m1 * D + e0] = (a0 && e0 != m1) ? nv0 : MAXD;
        if (e1 < D) g_Dm[(size_t)m1 * D + e1] = (a1 && e1 != m1) ? nv1 : MAXD;
        if (a0 && e0 != m1) g_Dm[(size_t)e0 * D + m1] = nv0;
        if (a1 && e1 != m1) g_Dm[(size_t)e1 * D + m1] = nv1;

        // m1-row min partial (redux)
        {
            float rv; int ri;
            wargmin(m1best, m1bi, rv, ri);
            if (lane == 0) { s_mv[wid] = rv; s_mi[wid] = ri; }
        }
        // owner pre-reduce for global argmin (local final values; exclude rescanned/m1)
        {
            float gv; int gi;
            if (v1f < v0f) { gv = v1f; gi = e1; } else { gv = v0f; gi = e0; }  // e0<e1: leftmost
            float rv; int ri;
            wargmin(gv, gi, rv, ri);
            if (lane == 0) { s_pv[wid] = rv; s_pi[wid] = ri; }
        }
        if (need0) { int p = atomicAdd(&s_nresc, 1); s_rlist[p] = e0; }
        if (need1) { int p = atomicAdd(&s_nresc, 1); s_rlist[p] = e1; }
        __syncthreads();   // B1

        // ==== Region2 (only if rescans): one warp per row
        const int nr = s_nresc;
        if (nr) {
            for (int t = wid; t < nr; t += NW) {
                int r = s_rlist[t];
                float bv = MAXD; int bbi = 0;
                if (vec4) {
                    const float4* row4 = reinterpret_cast<const float4*>(&g_Dm[(size_t)r * D]);
                    float4 qd[8];
                    #pragma unroll
                    for (int c = 0; c < 8; c++) {
                        int k = c * 128 + lane * 4;
                        if (k < D) qd[c] = row4[k >> 2];
                        else { qd[c].x = MAXD; qd[c].y = MAXD; qd[c].z = MAXD; qd[c].w = MAXD; }
                    }
                    #pragma unroll
                    for (int c = 0; c < 8; c++) {
                        int k = c * 128 + lane * 4;
                        unsigned a2 = (k < D) ? (s_amask[k >> 5] >> (k & 31)) : 0u;
                        float f0 = ((a2 & 1u) && k > r)       ? qd[c].x : MAXD;
                        float f1 = ((a2 & 2u) && (k + 1) > r) ? qd[c].y : MAXD;
                        float f2 = ((a2 & 4u) && (k + 2) > r) ? qd[c].z : MAXD;
                        float f3 = ((a2 & 8u) && (k + 3) > r) ? qd[c].w : MAXD;
                        if (f0 < bv) { bv = f0; bbi = k; }
                        if (f1 < bv) { bv = f1; bbi = k + 1; }
                        if (f2 < bv) { bv = f2; bbi = k + 2; }
                        if (f3 < bv) { bv = f3; bbi = k + 3; }
                    }
                } else {
                    const float* row = &g_Dm[(size_t)r * D];
                    for (int k = lane; k < D; k += 32) {
                        int alv = (s_amask[k >> 5] >> (k & 31)) & 1;
                        float vv = (alv && k > r) ? row[k] : MAXD;
                        if (vv < bv) { bv = vv; bbi = k; }
                    }
                }
                float rv; int ri;
                wargmin(bv, bbi, rv, ri);
                if (lane == 0) {
                    s_vals[r] = rv; s_idx[r] = ri;
                    s_cv[t] = rv; s_ci[t] = r;
                }
            }
            __syncthreads();   // B2 (skipped when nr==0)
        }

        // ==== Region3: parallel across warps 0 (select), 1 (take/records), 2 (pool)
        if (wid == 0) {
            float mv; int mi;
            {
                float v = (lane < NW) ? s_mv[lane] : MAXD;
                int i = (lane < NW) ? s_mi[lane] : NEUT;
                wargmin(v, i, mv, mi);
            }
            float gv; int gi;
            {
                float v = (lane < NW) ? s_pv[lane] : MAXD;
                int i = (lane < NW) ? s_pi[lane] : NEUT;
                for (int t = lane; t < nr; t += 32) {
                    float cv = s_cv[t]; int ci = s_ci[t];
                    if (cv < v || (cv == v && ci < i)) { v = cv; i = ci; }
                }
                wargmin(v, i, gv, gi);
            }
            if (lane == 0) {
                if (mi >= D) mi = 0;
                s_vals[m1] = mv; s_idx[m1] = mi;
                if (mv < gv || (mv == gv && m1 < gi)) { gv = mv; gi = m1; }
                if (gi >= D) gi = 0;
                int n1 = gi, n2 = s_idx[n1];
                s_m1 = n1; s_m2 = n2;
                float c1 = s_cs[n1], c2 = s_cs[n2];
                float nn = __fadd_rn(c1, c2);
                s_cs1 = c1; s_cs2 = c2; s_ncs = nn;
                s_cs[n1] = nn;
                s_vals[n2] = MAXD;
                s_amask[n2 >> 5] &= ~(1u << (n2 & 31));
                s_nresc = 0;
            }
        } else if (wid == 1) {
            float cw = (lane < NW) ? s_pw[lane] : 0.f;
            #pragma unroll
            for (int o = 8; o; o >>= 1) cw = __fadd_rn(cw, __shfl_xor_sync(~0u, cw, o));
            if (lane == 0) {
                float me = __fadd_rn(__fadd_rn(s_within[m1], s_within[m2]), cw);
                float es = __fadd_rn(s_energy[m1], s_energy[m2]);
                int take = (me >= es) ? 1 : 0;
                s_within[m1] = me;
                s_energy[m1] = take ? me : es;
                g_take[it] = take;
                g_rec[it] = make_int4(aOff, aLen, bOff, bLen);
                g_parent[it] = -1;
                int na = g_node[m1], nb = g_node[m2];
                if (na >= 0) g_parent[na] = it;
                if (nb >= 0) g_parent[nb] = it;
                g_node[m1] = it;
            }
        } else if (wid == 2) {
            int dst = 0, src = 0, ncopy = 0, dst2 = 0, src2 = 0, ncopy2 = 0;
            if (lane == 0) {
                int lenN = aLen + bLen;
                if (lenN <= s_cap[m1]) {
                    dst = aOff + aLen; src = bOff; ncopy = bLen;
                } else if (lenN <= s_cap[m2]) {
                    dst = bOff + bLen; src = aOff; ncopy = aLen;
                    s_off[m1] = bOff; s_cap[m1] = s_cap[m2];
                } else {
                    int nc = 1; while (nc < lenN) nc <<= 1;
                    int nb2 = s_ptop; s_ptop = nb2 + nc;
                    dst = nb2; src = aOff; ncopy = aLen;
                    dst2 = nb2 + aLen; src2 = bOff; ncopy2 = bLen;
                    s_off[m1] = nb2; s_cap[m1] = nc;
                }
                s_len[m1] = lenN;
            }
            dst = __shfl_sync(~0u, dst, 0);   src = __shfl_sync(~0u, src, 0);
            ncopy = __shfl_sync(~0u, ncopy, 0);
            dst2 = __shfl_sync(~0u, dst2, 0); src2 = __shfl_sync(~0u, src2, 0);
            ncopy2 = __shfl_sync(~0u, ncopy2, 0);
            for (int t = lane; t < ncopy; t += 32) g_pool[dst + t] = g_pool[src + t];
            for (int t = lane; t < ncopy2; t += 32) g_pool[dst2 + t] = g_pool[src2 + t];
        }
        __syncthreads();   // B3
    }

    // ==== coverage pass: cov[it] = take[it] || cov[parent[it]]  (parent > it)
    for (int k = j; k < D - 1; k += NT) { s_rlist[k] = g_parent[k]; s_ci[k] = g_take[k]; }
    __syncthreads();
    if (j == 0) {
        for (int n = D - 2; n >= 0; --n) {
            int p = s_rlist[n];
            int c = s_ci[n];
            if (!c && p >= 0) c = s_idx[p];   // s_idx reused as cov array
            s_idx[n] = c;
        }
    }
    __syncthreads();
    for (int k = j; k < D - 1; k += NT) g_cov[k] = s_idx[k];
}

// Paint: one block per merge node; covered nodes write their A x B cross block.
__global__ void k_paint(float* __restrict__ R, int D) {
    int n = blockIdx.x;
    if (!g_cov[n]) return;
    int4 rc = g_rec[n];
    int wid = threadIdx.x >> 5, lane = threadIdx.x & 31;
    for (int ia = wid; ia < rc.y; ia += 8) {
        int a = g_pool[rc.x + ia];
        float* ra = R + (size_t)a * D;
        for (int ib = lane; ib < rc.w; ib += 32) {
            int b = g_pool[rc.z + ib];
            ra[b] = 1.0f;
            R[(size_t)b * D + a] = 1.0f;
        }
    }
}

extern "C" void kernel_launch(void* const* d_in, const int* in_sizes, int n_in,
                              void* d_out, int out_size) {
    const float* X = (const float*)d_in[0];
    const float* W = (const float*)d_in[1];
    float* R = (float*)d_out;
    int n = in_sizes[0];
    int D = (int)(sqrt((double)n) + 0.5);
    if (D < 2 || D > MAXDIM) return;

    k_reset<<<1, 1>>>();
    k_maxred<<<256, 256>>>(X, n);
    k_init<<<D, 256>>>(X, R, D);
    k_hac<<<1, NT>>>(W, D);
    k_paint<<<D - 1, 256>>>(R, D);
}